// round 7
// baseline (speedup 1.0000x reference)
#include <cuda_runtime.h>
#include <cuda_fp16.h>
#include <cstdint>
#include <math.h>

// Problem constants
#define N_GLOB 256
#define M_GLOB 1024
#define D_GLOB 512
#define H_GLOB 512

// Tiling
#define E_SUB    32
#define S_SUB    8
#define P_TILE   256          // pairs per CTA = 32e x 8s
#define H_TILE   128          // H per pass (4 passes)
#define K_SLAB   32           // K per phase
#define N_PHASES 64           // 4 passes * 16 k-slabs
#define N_STAGES 4

#define THREADS  320          // 256 consumers (8 warps, 64x64 tiles) + 64 producers (2 warps)
#define NCONS    256

// SMEM layout (byte offsets)
#define MBAR_OFF 0            // full[4] @ 0,8,16,24 ; empty[4] @ 32,40,48,56
#define B1_OFF   128          // 512 f32
#define W2_OFF   2176         // 512 f32
#define PART_OFF 4224         // 256 f32
#define ES_OFF   5248         // [32][520] half  (33280 B)
#define SS_OFF   38528        // [8][520] half   (8320 B)
#define A_OFF    46848        // 4 x 16384 B (frag-major: [pid(32)][lane(32)][16B])
#define B_OFF    112384       // 4 x [128][40] half (10240 B each)
#define SMEM_BYTES 153344

#define B_PADH   40           // halfs per B row (32 data + 8 pad), 80 B, 16B-aligned

__device__ static __half g_W1T[H_GLOB * D_GLOB];   // W1 transposed [h][k], fp16

__device__ __forceinline__ uint32_t smem_u32(const void* p) {
    uint32_t a;
    asm("{ .reg .u64 t; cvta.to.shared.u64 t, %1; cvt.u32.u64 %0, t; }" : "=r"(a) : "l"(p));
    return a;
}
__device__ __forceinline__ void cpa16(uint32_t s, const void* g) {
    asm volatile("cp.async.cg.shared.global [%0], [%1], 16;" :: "r"(s), "l"(g));
}
#define MBARRIER_INIT(addr, cnt) \
    asm volatile("mbarrier.init.shared.b64 [%0], %1;" :: "r"((uint32_t)(addr)), "r"((uint32_t)(cnt)) : "memory")
#define MBARRIER_ARRIVE(addr) \
    asm volatile("mbarrier.arrive.shared.b64 _, [%0];" :: "r"((uint32_t)(addr)) : "memory")
#define CPASYNC_MBAR_ARRIVE(addr) \
    asm volatile("cp.async.mbarrier.arrive.noinc.shared.b64 [%0];" :: "r"((uint32_t)(addr)) : "memory")
#define MBARRIER_WAIT_PARITY(addr, parity) do { \
    uint32_t _m = (uint32_t)(addr); uint32_t _p = (uint32_t)(parity); uint32_t _d; \
    asm volatile("{\n\t.reg .pred p;\n\t" \
        "mbarrier.try_wait.parity.acquire.cta.shared::cta.b64 p, [%1], %2;\n\t" \
        "selp.b32 %0, 1, 0, p;\n\t}" : "=r"(_d) : "r"(_m), "r"(_p) : "memory"); \
    if (!_d) { \
        asm volatile("{\n\t.reg .pred P1;\n\t" \
            "WL_%=:\n\t" \
            "mbarrier.try_wait.parity.acquire.cta.shared::cta.b64 P1, [%0], %1, 0x989680;\n\t" \
            "@P1 bra.uni WD_%=;\n\t" \
            "bra.uni WL_%=;\n\t" \
            "WD_%=:\n\t}" :: "r"(_m), "r"(_p) : "memory"); \
    } } while (0)

__device__ __forceinline__ uint32_t h2_u32(__half2 h) {
    uint32_t u;
    __builtin_memcpy(&u, &h, 4);
    return u;
}

// ---- pre-kernel: W1 [D][H] f32  ->  g_W1T [H][D] fp16 ----
__global__ void convert_w1_kernel(const float* __restrict__ W1) {
    __shared__ float tile[32][33];
    const int kx = blockIdx.x * 32;
    const int hx = blockIdx.y * 32;
    const int x = threadIdx.x, y = threadIdx.y;   // 32 x 8
    #pragma unroll
    for (int i = 0; i < 32; i += 8)
        tile[y + i][x] = W1[(size_t)(kx + y + i) * H_GLOB + hx + x];
    __syncthreads();
    #pragma unroll
    for (int i = 0; i < 32; i += 8)
        g_W1T[(size_t)(hx + y + i) * D_GLOB + kx + x] = __float2half(tile[x][y + i]);
}

__global__ void __launch_bounds__(THREADS, 1)
support_ws_kernel(const float* __restrict__ E,   // [N, D]
                  const float* __restrict__ S,   // [M, D]
                  const float* __restrict__ B1,  // [H]
                  const float* __restrict__ W2,  // [H]
                  const float* __restrict__ B2,  // [1]
                  float* __restrict__ out)       // [N, M]
{
    extern __shared__ char smem[];
    __half* smE  = (__half*)(smem + ES_OFF);
    __half* smS  = (__half*)(smem + SS_OFF);
    float*  smB1 = (float*)(smem + B1_OFF);
    float*  smW2 = (float*)(smem + W2_OFF);
    float*  smP  = (float*)(smem + PART_OFF);
    const uint32_t smb = smem_u32(smem);

    const int tid  = threadIdx.x;
    const int wid  = tid >> 5;
    const int lane = tid & 31;

    const int n0 = blockIdx.y * E_SUB;
    const int m0 = blockIdx.x * S_SUB;

    // ---- prologue (all threads): mbarriers, E/S fp16 staging, b1/w2, partials ----
    if (tid == 0) {
        #pragma unroll
        for (int s = 0; s < N_STAGES; ++s) {
            MBARRIER_INIT(smb + MBAR_OFF + s * 8, 128);        // full: 64 STS + 64 cp.async
            MBARRIER_INIT(smb + MBAR_OFF + 32 + s * 8, NCONS); // empty: 256 consumer arrives
        }
    }
    // E: 32 rows x 512 -> fp16 [row][520]
    for (int i = tid; i < 8192; i += THREADS) {       // float2 chunks
        const int row = i >> 8, c = i & 255;
        const float2 v = *(const float2*)(E + (size_t)(n0 + row) * D_GLOB + c * 2);
        *(__half2*)(smE + row * 520 + c * 2) = __floats2half2_rn(v.x, v.y);
    }
    // S: 8 rows x 512
    for (int i = tid; i < 2048; i += THREADS) {
        const int row = i >> 8, c = i & 255;
        const float2 v = *(const float2*)(S + (size_t)(m0 + row) * D_GLOB + c * 2);
        *(__half2*)(smS + row * 520 + c * 2) = __floats2half2_rn(v.x, v.y);
    }
    for (int i = tid; i < 512; i += THREADS) { smB1[i] = B1[i]; smW2[i] = W2[i]; }
    if (tid < 256) smP[tid] = 0.f;
    __syncthreads();

    if (wid >= 8) {
        // ================= PRODUCER (2 warps, 64 threads) =================
        const int pw = wid - 8;           // 0..1
        const int pt = tid - NCONS;       // 0..63
        const int c  = lane & 3;
        const int r  = lane >> 2;

        for (int p = 0; p < N_PHASES; ++p) {
            const int st   = p & 3;
            const int ph   = (p >> 2) & 1;
            const int slab = p & 15;
            const int pass = p >> 4;

            MBARRIER_WAIT_PARITY(smb + MBAR_OFF + 32 + st * 8, ph ^ 1);  // wait empty

            // --- build A frags (fp16) into stage st ---
            char* stA = smem + A_OFF + st * 16384;
            #pragma unroll
            for (int j = 0; j < 16; ++j) {
                const int pid  = j * 2 + pw;       // 0..31
                const int mt_g = pid >> 1;
                const int kt   = pid & 1;
                const int row0 = mt_g * 2;
                const int kb   = slab * 32 + kt * 16 + c * 2;
                const __half2 e0  = *(const __half2*)(smE + row0 * 520 + kb);
                const __half2 e0b = *(const __half2*)(smE + row0 * 520 + kb + 8);
                const __half2 e1  = *(const __half2*)(smE + (row0 + 1) * 520 + kb);
                const __half2 e1b = *(const __half2*)(smE + (row0 + 1) * 520 + kb + 8);
                const __half2 s0  = *(const __half2*)(smS + r * 520 + kb);
                const __half2 s0b = *(const __half2*)(smS + r * 520 + kb + 8);
                uint4 v;
                v.x = h2_u32(__habs2(__hsub2(e0,  s0)));
                v.y = h2_u32(__habs2(__hsub2(e1,  s0)));
                v.z = h2_u32(__habs2(__hsub2(e0b, s0b)));
                v.w = h2_u32(__habs2(__hsub2(e1b, s0b)));
                *(uint4*)(stA + pid * 512 + lane * 16) = v;
            }
            MBARRIER_ARRIVE(smb + MBAR_OFF + st * 8);   // A visible (release)

            // --- B slab cp.async into stage st: [128 h][32 k] fp16 ---
            #pragma unroll
            for (int j = 0; j < 8; ++j) {
                const int idx = pt + j * 64;            // 0..511
                const int h = idx >> 2, q = idx & 3;
                cpa16(smb + B_OFF + st * 10240 + h * 80 + q * 16,
                      g_W1T + (size_t)(pass * H_TILE + h) * D_GLOB + slab * K_SLAB + q * 8);
            }
            CPASYNC_MBAR_ARRIVE(smb + MBAR_OFF + st * 8);  // arrives when cp.asyncs land
        }
    } else {
        // ============ CONSUMER (8 warps, 64 rows x 64 cols each) ============
        const int warp_m = wid & 3;       // 64-row quadrant
        const int warp_n = wid >> 2;      // 64-col half (0..1)
        const int c  = lane & 3;
        const int bn = warp_n * 64 + (lane >> 2);

        float acc[4][8][4];
        float psum[8];
        #pragma unroll
        for (int i = 0; i < 8; ++i) psum[i] = 0.f;

        for (int p = 0; p < N_PHASES; ++p) {
            const int st   = p & 3;
            const int ph   = (p >> 2) & 1;
            const int slab = p & 15;
            const int pass = p >> 4;

            MBARRIER_WAIT_PARITY(smb + MBAR_OFF + st * 8, ph);   // wait full

            if (slab == 0) {
                #pragma unroll
                for (int mt = 0; mt < 4; ++mt)
                    #pragma unroll
                    for (int nt = 0; nt < 8; ++nt)
                        #pragma unroll
                        for (int q = 0; q < 4; ++q) acc[mt][nt][q] = 0.f;
            }

            const char*   bA = smem + A_OFF + st * 16384;
            const __half* bB = (const __half*)(smem + B_OFF + st * 10240);
            #pragma unroll
            for (int kt = 0; kt < 2; ++kt) {
                uint4 af[4];
                #pragma unroll
                for (int mt = 0; mt < 4; ++mt)
                    af[mt] = *(const uint4*)(bA + (((warp_m * 4 + mt) * 2 + kt) * 32 + lane) * 16);
                const int kk = kt * 16 + c * 2;
                #pragma unroll
                for (int nt = 0; nt < 8; ++nt) {
                    uint32_t b0 = *(const uint32_t*)(bB + (bn + nt * 8) * B_PADH + kk);
                    uint32_t b1 = *(const uint32_t*)(bB + (bn + nt * 8) * B_PADH + kk + 8);
                    #pragma unroll
                    for (int mt = 0; mt < 4; ++mt) {
                        asm volatile(
                            "mma.sync.aligned.m16n8k16.row.col.f32.f16.f16.f32 "
                            "{%0,%1,%2,%3}, {%4,%5,%6,%7}, {%8,%9}, {%0,%1,%2,%3};\n"
                            : "+f"(acc[mt][nt][0]), "+f"(acc[mt][nt][1]),
                              "+f"(acc[mt][nt][2]), "+f"(acc[mt][nt][3])
                            : "r"(af[mt].x), "r"(af[mt].y), "r"(af[mt].z), "r"(af[mt].w),
                              "r"(b0), "r"(b1));
                    }
                }
            }
            MBARRIER_ARRIVE(smb + MBAR_OFF + 32 + st * 8);   // stage consumed

            if (slab == 15) {
                #pragma unroll
                for (int mt = 0; mt < 4; ++mt)
                    #pragma unroll
                    for (int nt = 0; nt < 8; ++nt) {
                        const int jg = pass * H_TILE + warp_n * 64 + nt * 8 + c * 2;
                        const float b1a = smB1[jg], b1b = smB1[jg + 1];
                        const float w2a = smW2[jg], w2b = smW2[jg + 1];
                        const float h0 = fmaxf(acc[mt][nt][0] + b1a, 0.f);
                        const float h1 = fmaxf(acc[mt][nt][1] + b1b, 0.f);
                        const float h2 = fmaxf(acc[mt][nt][2] + b1a, 0.f);
                        const float h3 = fmaxf(acc[mt][nt][3] + b1b, 0.f);
                        psum[mt * 2 + 0] += h0 * w2a + h1 * w2b;
                        psum[mt * 2 + 1] += h2 * w2a + h3 * w2b;
                    }
            }
        }

        // reduce across quad (k-cols of frag), then across n-warps via smem atomics
        #pragma unroll
        for (int i = 0; i < 8; ++i) {
            psum[i] += __shfl_xor_sync(0xffffffffu, psum[i], 1);
            psum[i] += __shfl_xor_sync(0xffffffffu, psum[i], 2);
        }
        if (c == 0) {
            const int r = lane >> 2;
            #pragma unroll
            for (int mt = 0; mt < 4; ++mt) {
                atomicAdd(&smP[warp_m * 64 + mt * 16 + r],     psum[mt * 2 + 0]);
                atomicAdd(&smP[warp_m * 64 + mt * 16 + r + 8], psum[mt * 2 + 1]);
            }
        }
    }

    __syncthreads();
    if (tid < P_TILE) {
        const float logit = smP[tid] + B2[0];
        const int n = n0 + (tid >> 3);
        const int m = m0 + (tid & 7);
        out[(size_t)n * M_GLOB + m] = 1.f / (1.f + expf(-logit));
    }
}

extern "C" void kernel_launch(void* const* d_in, const int* in_sizes, int n_in,
                              void* d_out, int out_size)
{
    const float* E  = (const float*)d_in[0];
    const float* S  = (const float*)d_in[1];
    const float* W1 = (const float*)d_in[2];
    const float* B1 = (const float*)d_in[3];
    const float* W2 = (const float*)d_in[4];
    const float* B2 = (const float*)d_in[5];
    float* out = (float*)d_out;

    convert_w1_kernel<<<dim3(16, 16), dim3(32, 8)>>>(W1);

    cudaFuncSetAttribute(support_ws_kernel,
                         cudaFuncAttributeMaxDynamicSharedMemorySize, SMEM_BYTES);
    dim3 grid(M_GLOB / S_SUB, N_GLOB / E_SUB);   // (128, 8) = 1024 CTAs
    support_ws_kernel<<<grid, THREADS, SMEM_BYTES>>>(E, S, B1, W2, B2, out);
}

// round 8
// speedup vs baseline: 1.4027x; 1.4027x over previous
#include <cuda_runtime.h>
#include <cuda_fp16.h>
#include <cstdint>
#include <math.h>

// Problem constants
#define N_GLOB 256
#define M_GLOB 1024
#define D_GLOB 512
#define H_GLOB 512

// Tiling
#define E_SUB    32
#define S_SUB    8
#define P_TILE   256          // pairs per CTA = 32e x 8s
#define H_TILE   128          // H per pass (4 passes)
#define K_SLAB   64           // K per phase (= 4 x k16)
#define N_PHASES 32           // 4 passes * 8 k-slabs
#define N_STAGES 3

#define THREADS  576          // 512 consumers (16 warps, 64x32) + 64 producers (2 warps)
#define NCONS    512

// SMEM layout (byte offsets)
#define MBAR_OFF 0            // full[3] @ 0,8,16 ; empty[3] @ 24,32,40
#define B1_OFF   128          // 512 f32
#define W2_OFF   2176         // 512 f32
#define PART_OFF 4224         // 256 f32
#define ES_OFF   5248         // [32][520] half  (33280 B)
#define SS_OFF   38528        // [8][520]  half  (8320 B)
#define STAGE_OFF 46848       // 3 stages x 51200 B
#define STAGE_BYTES 51200     // A: 64 pids x 512 B = 32768 ; B: 128 rows x 144 B = 18432
#define A_IN_STAGE  0
#define B_IN_STAGE  32768
#define SMEM_BYTES 200448

#define B_ROWB   144          // bytes per B row (64 data halfs + 8 pad)

__device__ static __half g_W1T[H_GLOB * D_GLOB];   // W1 transposed [h][k], fp16

__device__ __forceinline__ uint32_t smem_u32(const void* p) {
    uint32_t a;
    asm("{ .reg .u64 t; cvta.to.shared.u64 t, %1; cvt.u32.u64 %0, t; }" : "=r"(a) : "l"(p));
    return a;
}
__device__ __forceinline__ void cpa16(uint32_t s, const void* g) {
    asm volatile("cp.async.cg.shared.global [%0], [%1], 16;" :: "r"(s), "l"(g));
}
#define MBARRIER_INIT(addr, cnt) \
    asm volatile("mbarrier.init.shared.b64 [%0], %1;" :: "r"((uint32_t)(addr)), "r"((uint32_t)(cnt)) : "memory")
#define MBARRIER_ARRIVE(addr) \
    asm volatile("mbarrier.arrive.shared.b64 _, [%0];" :: "r"((uint32_t)(addr)) : "memory")
#define CPASYNC_MBAR_ARRIVE(addr) \
    asm volatile("cp.async.mbarrier.arrive.noinc.shared.b64 [%0];" :: "r"((uint32_t)(addr)) : "memory")
#define MBARRIER_WAIT_PARITY(addr, parity) do { \
    uint32_t _m = (uint32_t)(addr); uint32_t _p = (uint32_t)(parity); uint32_t _d; \
    asm volatile("{\n\t.reg .pred p;\n\t" \
        "mbarrier.try_wait.parity.acquire.cta.shared::cta.b64 p, [%1], %2;\n\t" \
        "selp.b32 %0, 1, 0, p;\n\t}" : "=r"(_d) : "r"(_m), "r"(_p) : "memory"); \
    if (!_d) { \
        asm volatile("{\n\t.reg .pred P1;\n\t" \
            "WL_%=:\n\t" \
            "mbarrier.try_wait.parity.acquire.cta.shared::cta.b64 P1, [%0], %1, 0x989680;\n\t" \
            "@P1 bra.uni WD_%=;\n\t" \
            "bra.uni WL_%=;\n\t" \
            "WD_%=:\n\t}" :: "r"(_m), "r"(_p) : "memory"); \
    } } while (0)

__device__ __forceinline__ uint32_t h2_u32(__half2 h) {
    uint32_t u;
    __builtin_memcpy(&u, &h, 4);
    return u;
}

// ---- pre-kernel: W1 [D][H] f32  ->  g_W1T [H][D] fp16 ----
__global__ void convert_w1_kernel(const float* __restrict__ W1) {
    __shared__ float tile[32][33];
    const int kx = blockIdx.x * 32;
    const int hx = blockIdx.y * 32;
    const int x = threadIdx.x, y = threadIdx.y;   // 32 x 8
    #pragma unroll
    for (int i = 0; i < 32; i += 8)
        tile[y + i][x] = W1[(size_t)(kx + y + i) * H_GLOB + hx + x];
    __syncthreads();
    #pragma unroll
    for (int i = 0; i < 32; i += 8)
        g_W1T[(size_t)(hx + y + i) * D_GLOB + kx + x] = __float2half(tile[x][y + i]);
}

__global__ void __launch_bounds__(THREADS, 1)
support_ws_kernel(const float* __restrict__ E,   // [N, D]
                  const float* __restrict__ S,   // [M, D]
                  const float* __restrict__ B1,  // [H]
                  const float* __restrict__ W2,  // [H]
                  const float* __restrict__ B2,  // [1]
                  float* __restrict__ out)       // [N, M]
{
    extern __shared__ char smem[];
    __half* smE  = (__half*)(smem + ES_OFF);
    __half* smS  = (__half*)(smem + SS_OFF);
    float*  smB1 = (float*)(smem + B1_OFF);
    float*  smW2 = (float*)(smem + W2_OFF);
    float*  smP  = (float*)(smem + PART_OFF);
    const uint32_t smb = smem_u32(smem);

    const int tid  = threadIdx.x;
    const int wid  = tid >> 5;
    const int lane = tid & 31;

    const int n0 = blockIdx.y * E_SUB;
    const int m0 = blockIdx.x * S_SUB;

    // ---- prologue: mbarriers, E/S fp16 staging, b1/w2, partials ----
    if (tid == 0) {
        #pragma unroll
        for (int s = 0; s < N_STAGES; ++s) {
            MBARRIER_INIT(smb + MBAR_OFF + s * 8, 128);        // full: 64 STS + 64 cp.async
            MBARRIER_INIT(smb + MBAR_OFF + 24 + s * 8, NCONS); // empty: 512 consumer arrives
        }
    }
    for (int i = tid; i < 8192; i += THREADS) {       // E -> fp16 [32][520]
        const int row = i >> 8, c = i & 255;
        const float2 v = *(const float2*)(E + (size_t)(n0 + row) * D_GLOB + c * 2);
        *(__half2*)(smE + row * 520 + c * 2) = __floats2half2_rn(v.x, v.y);
    }
    for (int i = tid; i < 2048; i += THREADS) {       // S -> fp16 [8][520]
        const int row = i >> 8, c = i & 255;
        const float2 v = *(const float2*)(S + (size_t)(m0 + row) * D_GLOB + c * 2);
        *(__half2*)(smS + row * 520 + c * 2) = __floats2half2_rn(v.x, v.y);
    }
    for (int i = tid; i < 512; i += THREADS) { smB1[i] = B1[i]; smW2[i] = W2[i]; }
    if (tid < 256) smP[tid] = 0.f;
    __syncthreads();

    if (wid >= 16) {
        // ================= PRODUCER (2 warps, 64 threads) =================
        const int pw = wid - 16;          // 0..1
        const int pt = tid - NCONS;       // 0..63
        const int c  = lane & 3;
        const int r  = lane >> 2;

        for (int p = 0; p < N_PHASES; ++p) {
            const int st    = p % 3;
            const int round = p / 3;
            const int slab  = p & 7;
            const int pass  = p >> 3;
            const uint32_t stg = smb + STAGE_OFF + st * STAGE_BYTES;

            MBARRIER_WAIT_PARITY(smb + MBAR_OFF + 24 + st * 8, (round & 1) ^ 1); // wait empty

            // --- build A frags (fp16) into stage st: 64 pids = (mt_g<<2)|kt ---
            char* stA = smem + STAGE_OFF + st * STAGE_BYTES + A_IN_STAGE;
            #pragma unroll 4
            for (int j = 0; j < 32; ++j) {
                const int pid  = j * 2 + pw;       // 0..63
                const int mt_g = pid >> 2;
                const int kt   = pid & 3;
                const int row0 = mt_g * 2;
                const int kb   = slab * 64 + kt * 16 + c * 2;
                const __half2 e0  = *(const __half2*)(smE + row0 * 520 + kb);
                const __half2 e0b = *(const __half2*)(smE + row0 * 520 + kb + 8);
                const __half2 e1  = *(const __half2*)(smE + (row0 + 1) * 520 + kb);
                const __half2 e1b = *(const __half2*)(smE + (row0 + 1) * 520 + kb + 8);
                const __half2 s0  = *(const __half2*)(smS + r * 520 + kb);
                const __half2 s0b = *(const __half2*)(smS + r * 520 + kb + 8);
                uint4 v;
                v.x = h2_u32(__habs2(__hsub2(e0,  s0)));
                v.y = h2_u32(__habs2(__hsub2(e1,  s0)));
                v.z = h2_u32(__habs2(__hsub2(e0b, s0b)));
                v.w = h2_u32(__habs2(__hsub2(e1b, s0b)));
                *(uint4*)(stA + pid * 512 + lane * 16) = v;
            }
            MBARRIER_ARRIVE(smb + MBAR_OFF + st * 8);   // A visible (release)

            // --- B slab cp.async into stage st: [128 h][64 k] fp16, row 144 B ---
            #pragma unroll
            for (int j = 0; j < 16; ++j) {
                const int idx = pt + j * 64;            // 0..1023
                const int h = idx >> 3, q = idx & 7;
                cpa16(stg + B_IN_STAGE + h * B_ROWB + q * 16,
                      g_W1T + (size_t)(pass * H_TILE + h) * D_GLOB + slab * K_SLAB + q * 8);
            }
            CPASYNC_MBAR_ARRIVE(smb + MBAR_OFF + st * 8);  // arrives when cp.asyncs land
        }
    } else {
        // ============ CONSUMER (16 warps, 64 rows x 32 cols each) ============
        const int warp_m = wid & 3;
        const int warp_n = wid >> 2;
        const int c  = lane & 3;
        // ldmatrix per-lane address pieces: g = lane>>3 selects matrix
        const int g    = lane >> 3;
        const int lrow = ((g >> 1) << 3) + (lane & 7);  // 0..15 within 16-row group
        const int lcol = (g & 1) * 8;                   // k offset 0 / 8

        float acc[4][4][4];
        float psum[8];
        #pragma unroll
        for (int i = 0; i < 8; ++i) psum[i] = 0.f;

        for (int p = 0; p < N_PHASES; ++p) {
            const int st    = p % 3;
            const int round = p / 3;
            const int slab  = p & 7;
            const int pass  = p >> 3;

            MBARRIER_WAIT_PARITY(smb + MBAR_OFF + st * 8, round & 1);   // wait full

            if (slab == 0) {
                #pragma unroll
                for (int mt = 0; mt < 4; ++mt)
                    #pragma unroll
                    for (int nt = 0; nt < 4; ++nt)
                        #pragma unroll
                        for (int q = 0; q < 4; ++q) acc[mt][nt][q] = 0.f;
            }

            const char*    bA = smem + STAGE_OFF + st * STAGE_BYTES + A_IN_STAGE;
            const uint32_t bB = smb + STAGE_OFF + st * STAGE_BYTES + B_IN_STAGE;
            #pragma unroll
            for (int kt = 0; kt < 4; ++kt) {
                uint4 af[4];
                #pragma unroll
                for (int mt = 0; mt < 4; ++mt)
                    af[mt] = *(const uint4*)(bA + (((warp_m * 4 + mt) * 4 + kt) * 32 + lane) * 16);
                uint32_t bq[4][2];
                #pragma unroll
                for (int j = 0; j < 2; ++j) {
                    const uint32_t addr = bB + (uint32_t)(warp_n * 32 + j * 16 + lrow) * B_ROWB
                                             + (uint32_t)(kt * 16 + lcol) * 2;
                    asm volatile(
                        "ldmatrix.sync.aligned.m8n8.x4.shared.b16 {%0, %1, %2, %3}, [%4];"
                        : "=r"(bq[j * 2][0]), "=r"(bq[j * 2][1]),
                          "=r"(bq[j * 2 + 1][0]), "=r"(bq[j * 2 + 1][1])
                        : "r"(addr));
                }
                #pragma unroll
                for (int mt = 0; mt < 4; ++mt)
                    #pragma unroll
                    for (int nt = 0; nt < 4; ++nt) {
                        asm volatile(
                            "mma.sync.aligned.m16n8k16.row.col.f32.f16.f16.f32 "
                            "{%0,%1,%2,%3}, {%4,%5,%6,%7}, {%8,%9}, {%0,%1,%2,%3};\n"
                            : "+f"(acc[mt][nt][0]), "+f"(acc[mt][nt][1]),
                              "+f"(acc[mt][nt][2]), "+f"(acc[mt][nt][3])
                            : "r"(af[mt].x), "r"(af[mt].y), "r"(af[mt].z), "r"(af[mt].w),
                              "r"(bq[nt][0]), "r"(bq[nt][1]));
                    }
            }
            MBARRIER_ARRIVE(smb + MBAR_OFF + 24 + st * 8);   // stage consumed

            if (slab == 7) {
                #pragma unroll
                for (int mt = 0; mt < 4; ++mt)
                    #pragma unroll
                    for (int nt = 0; nt < 4; ++nt) {
                        const int jg = pass * H_TILE + warp_n * 32 + nt * 8 + c * 2;
                        const float b1a = smB1[jg], b1b = smB1[jg + 1];
                        const float w2a = smW2[jg], w2b = smW2[jg + 1];
                        const float h0 = fmaxf(acc[mt][nt][0] + b1a, 0.f);
                        const float h1 = fmaxf(acc[mt][nt][1] + b1b, 0.f);
                        const float h2 = fmaxf(acc[mt][nt][2] + b1a, 0.f);
                        const float h3 = fmaxf(acc[mt][nt][3] + b1b, 0.f);
                        psum[mt * 2 + 0] += h0 * w2a + h1 * w2b;
                        psum[mt * 2 + 1] += h2 * w2a + h3 * w2b;
                    }
            }
        }

        // reduce across quad (k-cols of frag), then across n-warps via smem atomics
        #pragma unroll
        for (int i = 0; i < 8; ++i) {
            psum[i] += __shfl_xor_sync(0xffffffffu, psum[i], 1);
            psum[i] += __shfl_xor_sync(0xffffffffu, psum[i], 2);
        }
        if (c == 0) {
            const int r = lane >> 2;
            #pragma unroll
            for (int mt = 0; mt < 4; ++mt) {
                atomicAdd(&smP[warp_m * 64 + mt * 16 + r],     psum[mt * 2 + 0]);
                atomicAdd(&smP[warp_m * 64 + mt * 16 + r + 8], psum[mt * 2 + 1]);
            }
        }
    }

    __syncthreads();
    if (tid < P_TILE) {
        const float logit = smP[tid] + B2[0];
        const int n = n0 + (tid >> 3);
        const int m = m0 + (tid & 7);
        out[(size_t)n * M_GLOB + m] = 1.f / (1.f + expf(-logit));
    }
}

extern "C" void kernel_launch(void* const* d_in, const int* in_sizes, int n_in,
                              void* d_out, int out_size)
{
    const float* E  = (const float*)d_in[0];
    const float* S  = (const float*)d_in[1];
    const float* W1 = (const float*)d_in[2];
    const float* B1 = (const float*)d_in[3];
    const float* W2 = (const float*)d_in[4];
    const float* B2 = (const float*)d_in[5];
    float* out = (float*)d_out;

    convert_w1_kernel<<<dim3(16, 16), dim3(32, 8)>>>(W1);

    cudaFuncSetAttribute(support_ws_kernel,
                         cudaFuncAttributeMaxDynamicSharedMemorySize, SMEM_BYTES);
    dim3 grid(M_GLOB / S_SUB, N_GLOB / E_SUB);   // (128, 8) = 1024 CTAs
    support_ws_kernel<<<grid, THREADS, SMEM_BYTES>>>(E, S, B1, W2, B2, out);
}